// round 15
// baseline (speedup 1.0000x reference)
#include <cuda_runtime.h>

#define BATCH 8
#define NA 76725
#define NC 80
#define KC 256
#define CAP 4096
#define CAPS 2048
#define MAXT 200
#define BC (BATCH*NC)        // 640
#define NFLAT (NC*KC)        // 20480
#define TFILT 2.5f
#define COLBUF 512
#define SBLK 512

// k_filter tiling
#define FBLK 256
#define F4PT 24
#define CHUNK (FBLK*F4PT)            // 6144 float4 per block
#define N4B (NA*NC/4)                // 1,534,500 float4 per batch
#define BPB ((N4B + CHUNK - 1)/CHUNK) // 250
#define STAGE 1024

// ---------------- scratch (device globals; no allocations) ----------------
__device__ int    g_cnt[BC];                          // zero at load; self-cleaning
__device__ int    g_done[BATCH];                      // zero at load; self-cleaning
__device__ unsigned long long g_cand[(size_t)BC*CAP]; // (logit_bits<<32)|anchor
__device__ float  g_tsc [BC*KC];     // fallback only
__device__ int    g_tanc[BC*KC];     // fallback only
__device__ float  g_sel [BC*KC];     // kept ? sigmoid : -1
__device__ float4 g_box4[BC*KC];     // decoded corners

// ---------------- exact-rounding helpers ----------------------------------
__device__ __forceinline__ float mulrn(float a, float b){ return __fmul_rn(a,b); }
__device__ __forceinline__ float addrn(float a, float b){ return __fadd_rn(a,b); }
__device__ __forceinline__ float subrn(float a, float b){ return __fsub_rn(a,b); }

// XLA f32 tanh rational approximation, no FMA fusion.
__device__ __forceinline__ float xla_tanh(float x){
    float ax = fabsf(x);
    if (ax < 0.0004f) return x;
    float cx = fminf(fmaxf(x, -7.90531110763549805f), 7.90531110763549805f);
    float s = mulrn(cx, cx);
    float p = -2.76076847742355e-16f;
    p = addrn(mulrn(p, s),  2.00018790482477e-13f);
    p = addrn(mulrn(p, s), -8.60467152213735e-11f);
    p = addrn(mulrn(p, s),  5.12229709037114e-08f);
    p = addrn(mulrn(p, s),  1.48572235717979e-05f);
    p = addrn(mulrn(p, s),  6.37261928875436e-04f);
    p = addrn(mulrn(p, s),  4.89352455891786e-03f);
    p = mulrn(cx, p);
    float q = 1.19825839466702e-06f;
    q = addrn(mulrn(q, s), 1.18534705686654e-04f);
    q = addrn(mulrn(q, s), 2.26843463243900e-03f);
    q = addrn(mulrn(q, s), 4.89352518554385e-03f);
    return __fdiv_rn(p, q);
}
__device__ __forceinline__ float xla_sigmoid(float x){
    return addrn(0.5f, mulrn(0.5f, xla_tanh(mulrn(0.5f, x))));
}

__device__ __forceinline__ unsigned long long pack_key(float sig, unsigned int idx){
    return ((unsigned long long)__float_as_uint(sig) << 32) |
           (unsigned long long)(~idx);
}

// ---------------- warp-aggregated helpers (dense paths ONLY) ---------------
__device__ __forceinline__ int warp_agg_add(int* ctr, bool pred){
    unsigned act = __ballot_sync(0xFFFFFFFFu, pred);
    if (!act) return -1;
    int lane = threadIdx.x & 31;
    int leader = __ffs(act) - 1;
    int base = 0;
    if (lane == leader) base = atomicAdd(ctr, __popc(act));
    base = __shfl_sync(0xFFFFFFFFu, base, leader);
    return pred ? base + __popc(act & ((1u << lane) - 1)) : -1;
}

__device__ __forceinline__ void warp_hist_add(unsigned int* hist, unsigned int bin, bool valid){
    unsigned key = valid ? bin : 0xFFFFFFFFu;
    unsigned peers = __match_any_sync(0xFFFFFFFFu, key);
    int lane = threadIdx.x & 31;
    if (valid && (__ffs(peers) - 1) == lane)
        atomicAdd(&hist[bin], (unsigned)__popc(peers));
}

// ---------------- bitonic sort (descending) on shared u64 ------------------
__device__ __forceinline__ void bitonic_desc(unsigned long long* sk, int n, int tid, int bs){
    for (int k = 2; k <= n; k <<= 1){
        for (int j = k >> 1; j > 0; j >>= 1){
            for (int i = tid; i < n; i += bs){
                int ixj = i ^ j;
                if (ixj > i){
                    unsigned long long x = sk[i], y = sk[ixj];
                    bool swap = ((i & k) == 0) ? (x < y) : (x > y);
                    if (swap){ sk[i] = y; sk[ixj] = x; }
                }
            }
            __syncthreads();
        }
    }
}

__device__ __forceinline__ unsigned int flip_bits(unsigned int u){
    return u ^ ((u >> 31) ? 0xFFFFFFFFu : 0x80000000u);
}

// ---------------- K1 helpers: element scatter ------------------------------
__device__ __forceinline__ void filter_emit(float val, int a, int c, int b,
                                            unsigned long long* stage,
                                            int* shist, int* scnt){
    int p = atomicAdd(scnt, 1);
    if (p < STAGE){
        stage[p] = ((unsigned long long)__float_as_uint(val) << 32) |
                   ((unsigned long long)(unsigned)a << 7) | (unsigned)c;
        atomicAdd(&shist[c], 1);
    } else {
        int bc  = b*NC + c;
        int pos = atomicAdd(&g_cnt[bc], 1);
        if (pos < CAP)
            g_cand[(size_t)bc*CAP + pos] =
                ((unsigned long long)__float_as_uint(val) << 32) | (unsigned)a;
    }
}

// ---------------- K1: streaming filter, max-reduce fast path ---------------
__global__ __launch_bounds__(FBLK) void k_filter(const float* __restrict__ cls){
    __shared__ unsigned long long stage[STAGE];
    __shared__ int shist[NC];
    __shared__ int sbase[NC];
    __shared__ int scur [NC];
    __shared__ int scnt;
    int tid   = threadIdx.x;
    int b     = blockIdx.x / BPB;
    int chunk = blockIdx.x % BPB;

    for (int i = tid; i < NC; i += FBLK){ shist[i] = 0; scur[i] = 0; }
    if (tid == 0) scnt = 0;
    __syncthreads();

    const float4* src = reinterpret_cast<const float4*>(cls) + (size_t)b*N4B;
    int base4 = chunk*CHUNK + tid;

    #pragma unroll
    for (int half = 0; half < 3; half++){
        float4 r[8];
        #pragma unroll
        for (int k = 0; k < 8; k++){
            int i4 = base4 + (half*8 + k)*FBLK;
            if (i4 < N4B) r[k] = src[i4];
            else          r[k] = make_float4(-1e30f,-1e30f,-1e30f,-1e30f);
        }
        #pragma unroll
        for (int k = 0; k < 8; k++){
            float m = fmaxf(fmaxf(r[k].x, r[k].y), fmaxf(r[k].z, r[k].w));
            if (m > TFILT){
                int i4 = base4 + (half*8 + k)*FBLK;
                int e  = i4*4;
                int a  = e / NC;
                int c0 = e - a*NC;
                float vals[4] = {r[k].x, r[k].y, r[k].z, r[k].w};
                #pragma unroll
                for (int t = 0; t < 4; t++)
                    if (vals[t] > TFILT)
                        filter_emit(vals[t], a, c0 + t, b, stage, shist, &scnt);
            }
        }
    }
    __syncthreads();

    if (tid < NC){
        int n = shist[tid];
        if (n > 0) sbase[tid] = atomicAdd(&g_cnt[b*NC + tid], n);
    }
    __syncthreads();

    int m = scnt < STAGE ? scnt : STAGE;
    for (int i = tid; i < m; i += FBLK){
        unsigned long long s = stage[i];
        int c = (int)(s & 127u);
        unsigned int a  = (unsigned int)((s >> 7) & 0x1FFFFu);
        unsigned int vb = (unsigned int)(s >> 32);
        int off = sbase[c] + atomicAdd(&scur[c], 1);
        if (off < CAP)
            g_cand[(size_t)(b*NC + c)*CAP + off] =
                ((unsigned long long)vb << 32) | a;
    }
}

// ---- K2+K3+K4 fused: select + decode + NMS + (last block) global top-200 --
__global__ __launch_bounds__(SBLK) void k_select(const float* __restrict__ cls,
                                                 const float* __restrict__ bpred,
                                                 const float* __restrict__ anch,
                                                 float* __restrict__ out){
    __shared__ __align__(16) unsigned int ssig[CAPS]; // 8KB; phase2: sbox
    __shared__ unsigned int sidx[CAPS];               // 8KB; phase2: smask
    __shared__ unsigned long long keys[COLBUF];       // 4KB; also final list
    __shared__ unsigned int hist[256], rscan[256], wsum[8];
    __shared__ int s_bin, s_above, s_total, s_cnt, s_last;
    __shared__ unsigned int selig[8], skeep[8], sflag[8];

    int bc  = blockIdx.x;
    int tid = threadIdx.x;
    int b   = bc / NC;
    int cnt = g_cnt[bc];
    __syncthreads();
    if (tid == 0) g_cnt[bc] = 0;      // self-clean for next graph replay

    float sc = 0.f; int a = 0;
    bool ok = (cnt >= KC && cnt <= CAPS);
    if (ok){
        if (cnt <= COLBUF){
            for (int i = tid; i < COLBUF; i += SBLK){
                if (i < cnt){
                    unsigned long long cd = g_cand[(size_t)bc*CAP + i];
                    float sg = xla_sigmoid(__uint_as_float((unsigned int)(cd >> 32)));
                    keys[i] = pack_key(sg, (unsigned int)(cd & 0xFFFFFFFFu));
                } else keys[i] = 0ULL;
            }
            __syncthreads();
            bitonic_desc(keys, COLBUF, tid, SBLK);
        } else {
            int iters = (cnt + SBLK - 1)/SBLK;
            for (int it = 0; it < iters; it++){
                int i = it*SBLK + tid;
                if (i < cnt){
                    unsigned long long cd = g_cand[(size_t)bc*CAP + i];
                    float sg = xla_sigmoid(__uint_as_float((unsigned int)(cd >> 32)));
                    ssig[i] = __float_as_uint(sg);
                    sidx[i] = (unsigned int)(cd & 0xFFFFFFFFu);
                }
            }
            __syncthreads();

            unsigned int prefix = 0; int remaining = KC; int dshift = 0;
            for (int shift = 24; shift >= 0; shift -= 8){
                if (tid < 256) hist[tid] = 0u;
                __syncthreads();
                for (int it = 0; it < iters; it++){
                    int i = it*SBLK + tid;
                    bool valid = i < cnt;
                    unsigned int u = valid ? ssig[i] : 0u;
                    bool match = valid && (shift == 24 || (u >> (shift + 8)) == prefix);
                    warp_hist_add(hist, (u >> shift) & 0xFFu, match);
                }
                __syncthreads();
                if (tid < 256){
                    unsigned v = hist[tid];
                    #pragma unroll
                    for (int off = 1; off < 32; off <<= 1){
                        unsigned t = __shfl_down_sync(0xFFFFFFFFu, v, off);
                        if ((tid & 31) + off < 32) v += t;
                    }
                    if ((tid & 31) == 0) wsum[tid >> 5] = v;
                    rscan[tid] = v;
                }
                __syncthreads();
                if (tid < 256){
                    unsigned add = 0;
                    for (int ww = (tid >> 5) + 1; ww < 8; ww++) add += wsum[ww];
                    rscan[tid] += add;
                }
                __syncthreads();
                if (tid < 256){
                    int r  = (int)rscan[tid];
                    int rn = (tid == 255) ? 0 : (int)rscan[tid + 1];
                    if (r >= remaining && rn < remaining){
                        s_bin = tid; s_above = rn; s_total = r;
                    }
                }
                __syncthreads();
                int above_prev = KC - remaining;
                prefix = (prefix << 8) | (unsigned int)s_bin;
                remaining -= s_above;
                dshift = shift;
                if (above_prev + s_total <= COLBUF) break;
                __syncthreads();
            }

            if (tid == 0) s_cnt = 0;
            __syncthreads();
            for (int it = 0; it < iters; it++){
                int i = it*SBLK + tid;
                bool valid = (i < cnt) && ((ssig[i] >> dshift) >= prefix);
                int p = warp_agg_add(&s_cnt, valid);
                if (valid && p < COLBUF)
                    keys[p] = ((unsigned long long)ssig[i] << 32) |
                              (unsigned long long)(~sidx[i]);
            }
            __syncthreads();
            int m = s_cnt;
            if (m <= COLBUF){
                for (int i = tid; i < COLBUF; i += SBLK) if (i >= m) keys[i] = 0ULL;
                __syncthreads();
                bitonic_desc(keys, COLBUF, tid, SBLK);
            } else {
                ok = false;
            }
            __syncthreads();
        }
        if (ok && tid < KC){
            unsigned long long key = keys[tid];
            sc = __uint_as_float((unsigned int)(key >> 32));
            a  = (int)(~(unsigned int)key);
        }
        __syncthreads();
    }
    if (!ok){
        int bb = bc / NC, c = bc - bb*NC;
        const float* col = cls + (size_t)bb*NA*NC + c;
        unsigned long long* red = keys;
        unsigned long long cur = 0xFFFFFFFFFFFFFFFFULL;
        for (int r = 0; r < KC; r++){
            unsigned long long best = 0ULL;
            for (int ai = tid; ai < NA; ai += SBLK){
                float sg = xla_sigmoid(col[(size_t)ai*NC]);
                unsigned long long key = pack_key(sg, (unsigned int)ai);
                if (key < cur && key > best) best = key;
            }
            red[tid] = best; __syncthreads();
            for (int s = 256; s > 0; s >>= 1){
                if (tid < s && red[tid+s] > red[tid]) red[tid] = red[tid+s];
                __syncthreads();
            }
            cur = red[0];
            if (tid == 0){
                g_tsc [bc*KC + r] = __uint_as_float((unsigned int)(cur >> 32));
                g_tanc[bc*KC + r] = (int)(~(unsigned int)cur);
            }
            __syncthreads();
        }
        if (tid < KC){
            sc = g_tsc [bc*KC + tid];
            a  = g_tanc[bc*KC + tid];
        }
        __syncthreads();
    }

    // =========== phase 2: decode + NMS (reuse ssig/sidx regions) ===========
    float4*       sbox  = reinterpret_cast<float4*>(ssig);
    unsigned int* smask = sidx;

    if (tid < KC){
        float4 bp = reinterpret_cast<const float4*>(bpred)[(size_t)b*NA + a];
        float4 an = reinterpret_cast<const float4*>(anch)[a];

        float dx = mulrn(bp.x, 0.1f), dy = mulrn(bp.y, 0.1f);
        float dw = mulrn(bp.z, 0.2f), dh = mulrn(bp.w, 0.2f);
        float cx = addrn(mulrn(dx, an.z), an.x);
        float cy = addrn(mulrn(dy, an.w), an.y);
        float w  = mulrn(expf(dw), an.z);
        float h  = mulrn(expf(dh), an.w);
        float4 box;
        box.x = subrn(cx, mulrn(0.5f, w));
        box.y = subrn(cy, mulrn(0.5f, h));
        box.z = addrn(cx, mulrn(0.5f, w));
        box.w = addrn(cy, mulrn(0.5f, h));
        sbox[tid] = box;
        g_box4[bc*KC + tid] = box;

        unsigned int bal = __ballot_sync(0xFFFFFFFFu, sc > 0.5f);
        if ((tid & 31) == 0) selig[tid >> 5] = bal;
    } else {
        int row = tid - 256;
        #pragma unroll
        for (int w8 = 0; w8 < 8; w8++) smask[row*8 + w8] = 0u;
    }
    __syncthreads();

    // split pair enumeration: tid<256 -> cand=tid, d=1..64
    //                         tid>=256 -> cand=tid-256, d=65..128 (d=128 iff cand<128)
    {
        int cand = (tid < 256) ? tid : (tid - 256);
        int dlo  = (tid < 256) ? 1 : 65;
        int dhi  = (tid < 256) ? 64 : ((cand < 128) ? 128 : 127);
        float4 bx = sbox[cand];
        float  a1 = mulrn(subrn(bx.z, bx.x), subrn(bx.w, bx.y));
        #pragma unroll 2
        for (int d = dlo; d <= dhi; d++){
            int j = (cand + d) & 255;
            float4 o   = sbox[j];
            float iw   = fmaxf(subrn(fminf(bx.z, o.z), fmaxf(bx.x, o.x)), 0.0f);
            float ih   = fmaxf(subrn(fminf(bx.w, o.w), fmaxf(bx.y, o.y)), 0.0f);
            float inter= mulrn(iw, ih);
            if (inter > 0.0f){
                float a2 = mulrn(subrn(o.z, o.x), subrn(o.w, o.y));
                float un = fmaxf(subrn(addrn(a1, a2), inter), 1e-8f);
                float p  = mulrn(0.5f, un);
                bool sup;
                if      (inter > mulrn(p, 1.000002f)) sup = true;
                else if (inter < mulrn(p, 0.999998f)) sup = false;
                else    sup = (__fdiv_rn(inter, un) > 0.5f);
                if (sup){
                    int lo = cand < j ? cand : j;
                    int hi = cand < j ? j : cand;
                    atomicOr(&smask[lo*8 + (hi >> 5)], 1u << (hi & 31));
                }
            }
        }
    }
    __syncthreads();

    if (tid < 256){
        unsigned int rowOr = 0;
        #pragma unroll
        for (int w8 = 0; w8 < 8; w8++) rowOr |= smask[tid*8 + w8];
        unsigned int fb = __ballot_sync(0xFFFFFFFFu, rowOr != 0u);
        if ((tid & 31) == 0) sflag[tid >> 5] = fb;
    }
    __syncthreads();

    if (tid == 0){
        unsigned int keep[8];
        #pragma unroll
        for (int w8 = 0; w8 < 8; w8++) keep[w8] = selig[w8];
        #pragma unroll
        for (int w8 = 0; w8 < 8; w8++){
            unsigned int f = sflag[w8];
            while (f){
                int bit = __ffs(f) - 1;
                f &= f - 1;
                int i = w8*32 + bit;
                if ((keep[w8] >> bit) & 1u){
                    const unsigned int* mi = &smask[i*8];
                    #pragma unroll
                    for (int q = 0; q < 8; q++) keep[q] &= ~mi[q];
                }
            }
        }
        int kcnt = 0;
        #pragma unroll
        for (int w8 = 0; w8 < 8; w8++){
            unsigned int kk = keep[w8];
            if (kcnt >= MAXT){ kk = 0u; }
            else {
                int pc = __popc(kk);
                if (kcnt + pc > MAXT){
                    int need = MAXT - kcnt;
                    unsigned int outw = 0u;
                    for (int bit = 0; bit < 32 && need > 0; bit++){
                        if ((kk >> bit) & 1u){ outw |= 1u << bit; need--; }
                    }
                    kk = outw;
                }
            }
            kcnt += __popc(kk);
            skeep[w8] = kk;
        }
    }
    __syncthreads();
    if (tid < 256){
        unsigned int kw = skeep[tid >> 5];
        g_sel[bc*KC + tid] = ((kw >> (tid & 31)) & 1u) ? sc : -1.0f;
    }

    // =========== phase 3: last block of batch runs the global top-200 ======
    __threadfence();          // make this block's g_sel/g_box4 globally visible
    __syncthreads();          // tid0's atomic issues after all fences
    if (tid == 0){
        int old = atomicAdd(&g_done[b], 1);
        s_last = (old == NC - 1);
        if (s_last) g_done[b] = 0;       // self-clean (all arrived)
    }
    __syncthreads();
    if (!s_last) return;
    __threadfence();          // acquire: see all batch blocks' g_sel writes

    const float4* sel4 = reinterpret_cast<const float4*>(g_sel + b*NFLAT);
    unsigned long long* list = keys;     // reuse

    unsigned int prefix = 0; int remaining = MAXT; int dshift = 0;
    for (int shift = 24; shift >= 0; shift -= 8){
        if (tid < 256) hist[tid] = 0u;
        __syncthreads();
        #pragma unroll 2
        for (int k = 0; k < NFLAT/4/SBLK; k++){
            int i4 = k*SBLK + tid;
            float4 v = sel4[i4];
            unsigned int fk[4];
            fk[0] = flip_bits(__float_as_uint(v.x));
            fk[1] = flip_bits(__float_as_uint(v.y));
            fk[2] = flip_bits(__float_as_uint(v.z));
            fk[3] = flip_bits(__float_as_uint(v.w));
            #pragma unroll
            for (int q = 0; q < 4; q++){
                bool match = (shift == 24) || ((fk[q] >> (shift + 8)) == prefix);
                warp_hist_add(hist, (fk[q] >> shift) & 0xFFu, match);
            }
        }
        __syncthreads();
        if (tid < 256){
            unsigned v = hist[tid];
            #pragma unroll
            for (int off = 1; off < 32; off <<= 1){
                unsigned t = __shfl_down_sync(0xFFFFFFFFu, v, off);
                if ((tid & 31) + off < 32) v += t;
            }
            if ((tid & 31) == 0) wsum[tid >> 5] = v;
            rscan[tid] = v;
        }
        __syncthreads();
        if (tid < 256){
            unsigned add = 0;
            for (int ww = (tid >> 5) + 1; ww < 8; ww++) add += wsum[ww];
            rscan[tid] += add;
        }
        __syncthreads();
        if (tid < 256){
            int r  = (int)rscan[tid];
            int rn = (tid == 255) ? 0 : (int)rscan[tid + 1];
            if (r >= remaining && rn < remaining){
                s_bin = tid; s_above = rn; s_total = r;
            }
        }
        __syncthreads();
        int above_prev = MAXT - remaining;
        prefix = (prefix << 8) | (unsigned int)s_bin;
        remaining -= s_above;
        dshift = shift;
        if (above_prev + s_total <= COLBUF) break;
        __syncthreads();
    }

    if (tid == 0) s_cnt = 0;
    __syncthreads();
    #pragma unroll 2
    for (int k = 0; k < NFLAT/SBLK; k++){
        int i = k*SBLK + tid;
        unsigned int fk = flip_bits(__float_as_uint(g_sel[b*NFLAT + i]));
        bool valid = (fk >> dshift) >= prefix;
        int pos = warp_agg_add(&s_cnt, valid);
        if (valid && pos < COLBUF)
            list[pos] = ((unsigned long long)fk << 32) |
                        (unsigned long long)(~(unsigned int)i);
    }
    __syncthreads();
    int m2 = s_cnt < COLBUF ? s_cnt : COLBUF;
    for (int i = tid; i < COLBUF; i += SBLK) if (i >= m2) list[i] = 0ULL;
    __syncthreads();

    bitonic_desc(list, COLBUF, tid, SBLK);

    if (tid < MAXT){
        unsigned long long key = list[tid];
        unsigned int fk = (unsigned int)(key >> 32);
        unsigned int u  = (fk & 0x80000000u) ? (fk ^ 0x80000000u) : ~fk;
        float scv = __uint_as_float(u);
        int flat  = (int)(~(unsigned int)key);

        float4 bx = make_float4(0.f, 0.f, 0.f, 0.f);
        float  so = 0.f, lab = -1.f;
        if (scv > 0.0f && flat >= 0 && flat < NFLAT){
            int c    = flat >> 8;
            int slot = flat & 255;
            bx  = g_box4[(b*NC + c)*KC + slot];
            so  = scv;
            lab = (float)c;
        }
        float* ob = out;                       // [B, MAXT, 4]
        float* os = out + BATCH*MAXT*4;        // [B, MAXT]
        float* ol = out + BATCH*MAXT*5;        // [B, MAXT]
        reinterpret_cast<float4*>(ob)[b*MAXT + tid] = bx;
        os[b*MAXT + tid] = so;
        ol[b*MAXT + tid] = lab;
    }
}

// ---------------- launch ----------------------------------------------------
extern "C" void kernel_launch(void* const* d_in, const int* in_sizes, int n_in,
                              void* d_out, int out_size){
    const float* box_pred = (const float*)d_in[0];   // [B, A, 4]
    const float* cls_pred = (const float*)d_in[1];   // [B, A, C]
    const float* anchors  = (const float*)d_in[2];   // [A, 4]
    float* out = (float*)d_out;

    k_filter<<<BATCH*BPB, FBLK>>>(cls_pred);
    k_select<<<BC, SBLK>>>(cls_pred, box_pred, anchors, out);
}

// round 16
// speedup vs baseline: 1.1409x; 1.1409x over previous
#include <cuda_runtime.h>

#define BATCH 8
#define NA 76725
#define NC 80
#define KC 256
#define CAP 4096
#define CAPS 2048
#define MAXT 200
#define BC (BATCH*NC)        // 640
#define NFLAT (NC*KC)        // 20480
#define TFILT 2.5f
#define COLBUF 512
#define SBLK 512

// k_filter tiling
#define FBLK 256
#define F4PT 24
#define CHUNK (FBLK*F4PT)            // 6144 float4 per block
#define N4B (NA*NC/4)                // 1,534,500 float4 per batch
#define BPB ((N4B + CHUNK - 1)/CHUNK) // 250
#define STAGE 1024

// ---------------- scratch (device globals; no allocations) ----------------
__device__ int    g_cnt[BC];                          // zero at load; self-cleaning
__device__ unsigned long long g_cand[(size_t)BC*CAP]; // (logit_bits<<32)|anchor
__device__ float  g_tsc [BC*KC];     // fallback only
__device__ int    g_tanc[BC*KC];     // fallback only
__device__ float  g_sel [BC*KC];     // kept ? sigmoid : -1
__device__ float4 g_box4[BC*KC];     // decoded corners

// ---------------- exact-rounding helpers ----------------------------------
__device__ __forceinline__ float mulrn(float a, float b){ return __fmul_rn(a,b); }
__device__ __forceinline__ float addrn(float a, float b){ return __fadd_rn(a,b); }
__device__ __forceinline__ float subrn(float a, float b){ return __fsub_rn(a,b); }

// XLA f32 tanh rational approximation, no FMA fusion.
__device__ __forceinline__ float xla_tanh(float x){
    float ax = fabsf(x);
    if (ax < 0.0004f) return x;
    float cx = fminf(fmaxf(x, -7.90531110763549805f), 7.90531110763549805f);
    float s = mulrn(cx, cx);
    float p = -2.76076847742355e-16f;
    p = addrn(mulrn(p, s),  2.00018790482477e-13f);
    p = addrn(mulrn(p, s), -8.60467152213735e-11f);
    p = addrn(mulrn(p, s),  5.12229709037114e-08f);
    p = addrn(mulrn(p, s),  1.48572235717979e-05f);
    p = addrn(mulrn(p, s),  6.37261928875436e-04f);
    p = addrn(mulrn(p, s),  4.89352455891786e-03f);
    p = mulrn(cx, p);
    float q = 1.19825839466702e-06f;
    q = addrn(mulrn(q, s), 1.18534705686654e-04f);
    q = addrn(mulrn(q, s), 2.26843463243900e-03f);
    q = addrn(mulrn(q, s), 4.89352518554385e-03f);
    return __fdiv_rn(p, q);
}
__device__ __forceinline__ float xla_sigmoid(float x){
    return addrn(0.5f, mulrn(0.5f, xla_tanh(mulrn(0.5f, x))));
}

__device__ __forceinline__ unsigned long long pack_key(float sig, unsigned int idx){
    return ((unsigned long long)__float_as_uint(sig) << 32) |
           (unsigned long long)(~idx);
}

// ---------------- warp-aggregated helpers (dense paths ONLY) ---------------
__device__ __forceinline__ int warp_agg_add(int* ctr, bool pred){
    unsigned act = __ballot_sync(0xFFFFFFFFu, pred);
    if (!act) return -1;
    int lane = threadIdx.x & 31;
    int leader = __ffs(act) - 1;
    int base = 0;
    if (lane == leader) base = atomicAdd(ctr, __popc(act));
    base = __shfl_sync(0xFFFFFFFFu, base, leader);
    return pred ? base + __popc(act & ((1u << lane) - 1)) : -1;
}

__device__ __forceinline__ void warp_hist_add(unsigned int* hist, unsigned int bin, bool valid){
    unsigned key = valid ? bin : 0xFFFFFFFFu;
    unsigned peers = __match_any_sync(0xFFFFFFFFu, key);
    int lane = threadIdx.x & 31;
    if (valid && (__ffs(peers) - 1) == lane)
        atomicAdd(&hist[bin], (unsigned)__popc(peers));
}

// ---------------- bitonic sort (descending) on shared u64 ------------------
__device__ __forceinline__ void bitonic_desc(unsigned long long* sk, int n, int tid, int bs){
    for (int k = 2; k <= n; k <<= 1){
        for (int j = k >> 1; j > 0; j >>= 1){
            for (int i = tid; i < n; i += bs){
                int ixj = i ^ j;
                if (ixj > i){
                    unsigned long long x = sk[i], y = sk[ixj];
                    bool swap = ((i & k) == 0) ? (x < y) : (x > y);
                    if (swap){ sk[i] = y; sk[ixj] = x; }
                }
            }
            __syncthreads();
        }
    }
}

__device__ __forceinline__ unsigned int flip_bits(unsigned int u){
    return u ^ ((u >> 31) ? 0xFFFFFFFFu : 0x80000000u);
}

// ---------------- K1: streaming filter, max-reduce fast path ---------------
__global__ __launch_bounds__(FBLK) void k_filter(const float* __restrict__ cls){
    __shared__ unsigned long long stage[STAGE];
    __shared__ int shist[NC];
    __shared__ int sbase[NC];
    __shared__ int scur [NC];
    __shared__ int scnt;
    int tid   = threadIdx.x;
    int b     = blockIdx.x / BPB;
    int chunk = blockIdx.x % BPB;

    for (int i = tid; i < NC; i += FBLK){ shist[i] = 0; scur[i] = 0; }
    if (tid == 0) scnt = 0;
    __syncthreads();

    const float4* src = reinterpret_cast<const float4*>(cls) + (size_t)b*N4B;
    int base4 = chunk*CHUNK + tid;

    #pragma unroll
    for (int half = 0; half < 3; half++){
        float4 r[8];
        #pragma unroll
        for (int k = 0; k < 8; k++){
            int i4 = base4 + (half*8 + k)*FBLK;
            if (i4 < N4B) r[k] = __ldcs(&src[i4]);    // streaming: evict-first
            else          r[k] = make_float4(-1e30f,-1e30f,-1e30f,-1e30f);
        }
        #pragma unroll
        for (int k = 0; k < 8; k++){
            float m = fmaxf(fmaxf(r[k].x, r[k].y), fmaxf(r[k].z, r[k].w));
            if (m > TFILT){
                int i4 = base4 + (half*8 + k)*FBLK;
                int e  = i4*4;
                int a  = e / NC;
                int c0 = e - a*NC;            // multiple of 4
                float vals[4] = {r[k].x, r[k].y, r[k].z, r[k].w};
                #pragma unroll
                for (int t = 0; t < 4; t++){
                    if (vals[t] > TFILT){
                        int c = c0 + t;
                        int p = atomicAdd(&scnt, 1);
                        if (p < STAGE){
                            stage[p] =
                                ((unsigned long long)__float_as_uint(vals[t]) << 32) |
                                ((unsigned long long)(unsigned)a << 7) | (unsigned)c;
                            atomicAdd(&shist[c], 1);
                        } else {
                            int bc  = b*NC + c;
                            int pos = atomicAdd(&g_cnt[bc], 1);
                            if (pos < CAP)
                                g_cand[(size_t)bc*CAP + pos] =
                                    ((unsigned long long)__float_as_uint(vals[t]) << 32) |
                                    (unsigned)a;
                        }
                    }
                }
            }
        }
    }
    __syncthreads();

    if (tid < NC){
        int n = shist[tid];
        if (n > 0) sbase[tid] = atomicAdd(&g_cnt[b*NC + tid], n);
    }
    __syncthreads();

    int m = scnt < STAGE ? scnt : STAGE;
    for (int i = tid; i < m; i += FBLK){
        unsigned long long s = stage[i];
        int c = (int)(s & 127u);
        unsigned int a  = (unsigned int)((s >> 7) & 0x1FFFFu);
        unsigned int vb = (unsigned int)(s >> 32);
        int off = sbase[c] + atomicAdd(&scur[c], 1);
        if (off < CAP)
            g_cand[(size_t)(b*NC + c)*CAP + off] =
                ((unsigned long long)vb << 32) | a;
    }
}

// ---------------- K2+K3 fused: top-256 select + decode + NMS (512 thr) -----
__global__ __launch_bounds__(SBLK) void k_select(const float* __restrict__ cls,
                                                 const float* __restrict__ bpred,
                                                 const float* __restrict__ anch){
    __shared__ __align__(16) unsigned int ssig[CAPS]; // 8KB; phase2: sbox
    __shared__ unsigned int sidx[CAPS];               // 8KB; phase2: smask
    __shared__ unsigned long long keys[COLBUF];       // 4KB; fallback red buf
    __shared__ unsigned int hist[256], rscan[256], wsum[8];
    __shared__ int s_bin, s_above, s_total, s_cnt;
    __shared__ unsigned int selig[8], skeep[8], sflag[8];

    int bc  = blockIdx.x;
    int tid = threadIdx.x;
    int b   = bc / NC;
    int cnt = g_cnt[bc];
    __syncthreads();
    if (tid == 0) g_cnt[bc] = 0;      // self-clean for next graph replay

    float sc = 0.f; int a = 0;
    bool ok = (cnt >= KC && cnt <= CAPS);
    if (ok){
        if (cnt <= COLBUF){
            for (int i = tid; i < COLBUF; i += SBLK){
                if (i < cnt){
                    unsigned long long cd = g_cand[(size_t)bc*CAP + i];
                    float sg = xla_sigmoid(__uint_as_float((unsigned int)(cd >> 32)));
                    keys[i] = pack_key(sg, (unsigned int)(cd & 0xFFFFFFFFu));
                } else keys[i] = 0ULL;
            }
            __syncthreads();
            bitonic_desc(keys, COLBUF, tid, SBLK);
        } else {
            int iters = (cnt + SBLK - 1)/SBLK;
            for (int it = 0; it < iters; it++){
                int i = it*SBLK + tid;
                if (i < cnt){
                    unsigned long long cd = g_cand[(size_t)bc*CAP + i];
                    float sg = xla_sigmoid(__uint_as_float((unsigned int)(cd >> 32)));
                    ssig[i] = __float_as_uint(sg);
                    sidx[i] = (unsigned int)(cd & 0xFFFFFFFFu);
                }
            }
            __syncthreads();

            unsigned int prefix = 0; int remaining = KC; int dshift = 0;
            for (int shift = 24; shift >= 0; shift -= 8){
                if (tid < 256) hist[tid] = 0u;
                __syncthreads();
                for (int it = 0; it < iters; it++){
                    int i = it*SBLK + tid;
                    bool valid = i < cnt;
                    unsigned int u = valid ? ssig[i] : 0u;
                    bool match = valid && (shift == 24 || (u >> (shift + 8)) == prefix);
                    warp_hist_add(hist, (u >> shift) & 0xFFu, match);
                }
                __syncthreads();
                if (tid < 256){
                    unsigned v = hist[tid];
                    #pragma unroll
                    for (int off = 1; off < 32; off <<= 1){
                        unsigned t = __shfl_down_sync(0xFFFFFFFFu, v, off);
                        if ((tid & 31) + off < 32) v += t;
                    }
                    if ((tid & 31) == 0) wsum[tid >> 5] = v;
                    rscan[tid] = v;
                }
                __syncthreads();
                if (tid < 256){
                    unsigned add = 0;
                    for (int ww = (tid >> 5) + 1; ww < 8; ww++) add += wsum[ww];
                    rscan[tid] += add;
                }
                __syncthreads();
                if (tid < 256){
                    int r  = (int)rscan[tid];
                    int rn = (tid == 255) ? 0 : (int)rscan[tid + 1];
                    if (r >= remaining && rn < remaining){
                        s_bin = tid; s_above = rn; s_total = r;
                    }
                }
                __syncthreads();
                int above_prev = KC - remaining;
                prefix = (prefix << 8) | (unsigned int)s_bin;
                remaining -= s_above;
                dshift = shift;
                if (above_prev + s_total <= COLBUF) break;
                __syncthreads();
            }

            if (tid == 0) s_cnt = 0;
            __syncthreads();
            for (int it = 0; it < iters; it++){
                int i = it*SBLK + tid;
                bool valid = (i < cnt) && ((ssig[i] >> dshift) >= prefix);
                int p = warp_agg_add(&s_cnt, valid);
                if (valid && p < COLBUF)
                    keys[p] = ((unsigned long long)ssig[i] << 32) |
                              (unsigned long long)(~sidx[i]);
            }
            __syncthreads();
            int m = s_cnt;
            if (m <= COLBUF){
                for (int i = tid; i < COLBUF; i += SBLK) if (i >= m) keys[i] = 0ULL;
                __syncthreads();
                bitonic_desc(keys, COLBUF, tid, SBLK);
            } else {
                ok = false;
            }
            __syncthreads();
        }
        if (ok && tid < KC){
            unsigned long long key = keys[tid];
            sc = __uint_as_float((unsigned int)(key >> 32));
            a  = (int)(~(unsigned int)key);
        }
        __syncthreads();
    }
    if (!ok){
        int bb = bc / NC, c = bc - bb*NC;
        const float* col = cls + (size_t)bb*NA*NC + c;
        unsigned long long* red = keys;      // 512 entries
        unsigned long long cur = 0xFFFFFFFFFFFFFFFFULL;
        for (int r = 0; r < KC; r++){
            unsigned long long best = 0ULL;
            for (int ai = tid; ai < NA; ai += SBLK){
                float sg = xla_sigmoid(col[(size_t)ai*NC]);
                unsigned long long key = pack_key(sg, (unsigned int)ai);
                if (key < cur && key > best) best = key;
            }
            red[tid] = best; __syncthreads();
            for (int s = 256; s > 0; s >>= 1){
                if (tid < s && red[tid+s] > red[tid]) red[tid] = red[tid+s];
                __syncthreads();
            }
            cur = red[0];
            if (tid == 0){
                g_tsc [bc*KC + r] = __uint_as_float((unsigned int)(cur >> 32));
                g_tanc[bc*KC + r] = (int)(~(unsigned int)cur);
            }
            __syncthreads();
        }
        if (tid < KC){
            sc = g_tsc [bc*KC + tid];
            a  = g_tanc[bc*KC + tid];
        }
        __syncthreads();
    }

    // =========== phase 2: decode + NMS (reuse ssig/sidx regions) ===========
    float4*       sbox  = reinterpret_cast<float4*>(ssig);
    unsigned int* smask = sidx;

    if (tid < KC){
        float4 bp = reinterpret_cast<const float4*>(bpred)[(size_t)b*NA + a];
        float4 an = reinterpret_cast<const float4*>(anch)[a];

        float dx = mulrn(bp.x, 0.1f), dy = mulrn(bp.y, 0.1f);
        float dw = mulrn(bp.z, 0.2f), dh = mulrn(bp.w, 0.2f);
        float cx = addrn(mulrn(dx, an.z), an.x);
        float cy = addrn(mulrn(dy, an.w), an.y);
        float w  = mulrn(expf(dw), an.z);
        float h  = mulrn(expf(dh), an.w);
        float4 box;
        box.x = subrn(cx, mulrn(0.5f, w));
        box.y = subrn(cy, mulrn(0.5f, h));
        box.z = addrn(cx, mulrn(0.5f, w));
        box.w = addrn(cy, mulrn(0.5f, h));
        sbox[tid] = box;
        g_box4[bc*KC + tid] = box;

        unsigned int bal = __ballot_sync(0xFFFFFFFFu, sc > 0.5f);
        if ((tid & 31) == 0) selig[tid >> 5] = bal;
    } else {
        int row = tid - 256;
        #pragma unroll
        for (int w8 = 0; w8 < 8; w8++) smask[row*8 + w8] = 0u;
    }
    __syncthreads();

    // split pair enumeration: tid<256 -> cand=tid, d=1..64
    //                         tid>=256 -> cand=tid-256, d=65..128 (d=128 iff cand<128)
    {
        int cand = (tid < 256) ? tid : (tid - 256);
        int dlo  = (tid < 256) ? 1 : 65;
        int dhi  = (tid < 256) ? 64 : ((cand < 128) ? 128 : 127);
        float4 bx = sbox[cand];
        float  a1 = mulrn(subrn(bx.z, bx.x), subrn(bx.w, bx.y));
        #pragma unroll 2
        for (int d = dlo; d <= dhi; d++){
            int j = (cand + d) & 255;
            float4 o   = sbox[j];
            float iw   = fmaxf(subrn(fminf(bx.z, o.z), fmaxf(bx.x, o.x)), 0.0f);
            float ih   = fmaxf(subrn(fminf(bx.w, o.w), fmaxf(bx.y, o.y)), 0.0f);
            float inter= mulrn(iw, ih);
            if (inter > 0.0f){
                float a2 = mulrn(subrn(o.z, o.x), subrn(o.w, o.y));
                float un = fmaxf(subrn(addrn(a1, a2), inter), 1e-8f);
                float p  = mulrn(0.5f, un);
                bool sup;
                if      (inter > mulrn(p, 1.000002f)) sup = true;
                else if (inter < mulrn(p, 0.999998f)) sup = false;
                else    sup = (__fdiv_rn(inter, un) > 0.5f);
                if (sup){
                    int lo = cand < j ? cand : j;
                    int hi = cand < j ? j : cand;
                    atomicOr(&smask[lo*8 + (hi >> 5)], 1u << (hi & 31));
                }
            }
        }
    }
    __syncthreads();

    if (tid < 256){
        unsigned int rowOr = 0;
        #pragma unroll
        for (int w8 = 0; w8 < 8; w8++) rowOr |= smask[tid*8 + w8];
        unsigned int fb = __ballot_sync(0xFFFFFFFFu, rowOr != 0u);
        if ((tid & 31) == 0) sflag[tid >> 5] = fb;
    }
    __syncthreads();

    if (tid == 0){
        unsigned int keep[8];
        #pragma unroll
        for (int w8 = 0; w8 < 8; w8++) keep[w8] = selig[w8];
        // sparse greedy: only flag-set rows can suppress; liveness checked at visit
        #pragma unroll
        for (int w8 = 0; w8 < 8; w8++){
            unsigned int f = sflag[w8];
            while (f){
                int bit = __ffs(f) - 1;
                f &= f - 1;
                int i = w8*32 + bit;
                if ((keep[w8] >> bit) & 1u){
                    const unsigned int* mi = &smask[i*8];
                    #pragma unroll
                    for (int q = 0; q < 8; q++) keep[q] &= ~mi[q];
                }
            }
        }
        int kcnt = 0;
        #pragma unroll
        for (int w8 = 0; w8 < 8; w8++){
            unsigned int kk = keep[w8];
            if (kcnt >= MAXT){ kk = 0u; }
            else {
                int pc = __popc(kk);
                if (kcnt + pc > MAXT){
                    int need = MAXT - kcnt;
                    unsigned int outw = 0u;
                    for (int bit = 0; bit < 32 && need > 0; bit++){
                        if ((kk >> bit) & 1u){ outw |= 1u << bit; need--; }
                    }
                    kk = outw;
                }
            }
            kcnt += __popc(kk);
            skeep[w8] = kk;
        }
    }
    __syncthreads();
    if (tid < 256){
        unsigned int kw = skeep[tid >> 5];
        g_sel[bc*KC + tid] = ((kw >> (tid & 31)) & 1u) ? sc : -1.0f;
    }
}

// ---------------- K4: per-batch global top-200 + output --------------------
__global__ __launch_bounds__(1024) void k_final(float* __restrict__ out){
    extern __shared__ unsigned int sfk[];          // NFLAT flipped keys (80KB)
    __shared__ unsigned int hist[256], rscan[256], wsum[8];
    __shared__ unsigned long long list[COLBUF];
    __shared__ int s_cnt, s_bin, s_above, s_total, s_pos;
    int b   = blockIdx.x;
    int tid = threadIdx.x;
    const float4* sel4 = reinterpret_cast<const float4*>(g_sel + b*NFLAT);

    if (tid == 0) s_pos = 0;
    __syncthreads();

    // stage flipped keys; count positives (kept => sigmoid>0.5 => top byte 0xBF)
    int npos = 0;
    #pragma unroll
    for (int k = 0; k < NFLAT/4/1024; k++){
        int i4 = k*1024 + tid;
        float4 v = sel4[i4];
        unsigned int f0 = flip_bits(__float_as_uint(v.x));
        unsigned int f1 = flip_bits(__float_as_uint(v.y));
        unsigned int f2 = flip_bits(__float_as_uint(v.z));
        unsigned int f3 = flip_bits(__float_as_uint(v.w));
        sfk[i4*4 + 0] = f0; sfk[i4*4 + 1] = f1;
        sfk[i4*4 + 2] = f2; sfk[i4*4 + 3] = f3;
        npos += (f0 >= 0xBF000000u) + (f1 >= 0xBF000000u)
              + (f2 >= 0xBF000000u) + (f3 >= 0xBF000000u);
    }
    #pragma unroll
    for (int off = 16; off > 0; off >>= 1)
        npos += __shfl_down_sync(0xFFFFFFFFu, npos, off);
    if ((tid & 31) == 0 && npos) atomicAdd(&s_pos, npos);
    __syncthreads();

    // radix-select; skip pass 1 when the 0xBF bucket alone holds >= MAXT keys
    unsigned int prefix; int startshift;
    if (s_pos >= MAXT){ prefix = 0xBFu; startshift = 16; }
    else              { prefix = 0u;    startshift = 24; }
    int remaining = MAXT; int dshift = startshift;
    for (int shift = startshift; shift >= 0; shift -= 8){
        if (tid < 256) hist[tid] = 0u;
        __syncthreads();
        #pragma unroll
        for (int k = 0; k < NFLAT/1024; k++){
            int i = k*1024 + tid;
            unsigned int fk = sfk[i];
            bool match = (shift == 24) || ((fk >> (shift + 8)) == prefix);
            warp_hist_add(hist, (fk >> shift) & 0xFFu, match);
        }
        __syncthreads();
        if (tid < 256){
            unsigned v = hist[tid];
            #pragma unroll
            for (int off = 1; off < 32; off <<= 1){
                unsigned t = __shfl_down_sync(0xFFFFFFFFu, v, off);
                if ((tid & 31) + off < 32) v += t;
            }
            if ((tid & 31) == 0) wsum[tid >> 5] = v;
            rscan[tid] = v;
        }
        __syncthreads();
        if (tid < 256){
            unsigned add = 0;
            for (int ww = (tid >> 5) + 1; ww < 8; ww++) add += wsum[ww];
            rscan[tid] += add;
        }
        __syncthreads();
        if (tid < 256){
            int r  = (int)rscan[tid];
            int rn = (tid == 255) ? 0 : (int)rscan[tid + 1];
            if (r >= remaining && rn < remaining){
                s_bin = tid; s_above = rn; s_total = r;
            }
        }
        __syncthreads();
        int above_prev = MAXT - remaining;
        prefix = (prefix << 8) | (unsigned int)s_bin;
        remaining -= s_above;
        dshift = shift;
        if (above_prev + s_total <= COLBUF) break;
        __syncthreads();
    }

    if (tid == 0) s_cnt = 0;
    __syncthreads();
    #pragma unroll
    for (int k = 0; k < NFLAT/1024; k++){
        int i = k*1024 + tid;
        unsigned int fk = sfk[i];
        bool valid = (fk >> dshift) >= prefix;
        int pos = warp_agg_add(&s_cnt, valid);
        if (valid && pos < COLBUF)
            list[pos] = ((unsigned long long)fk << 32) |
                        (unsigned long long)(~(unsigned int)i);
    }
    __syncthreads();
    int m = s_cnt < COLBUF ? s_cnt : COLBUF;
    for (int i = tid; i < COLBUF; i += 1024) if (i >= m) list[i] = 0ULL;
    __syncthreads();

    bitonic_desc(list, COLBUF, tid, 1024);

    if (tid < MAXT){
        unsigned long long key = list[tid];
        unsigned int fk = (unsigned int)(key >> 32);
        unsigned int u  = (fk & 0x80000000u) ? (fk ^ 0x80000000u) : ~fk;
        float scv = __uint_as_float(u);
        int flat  = (int)(~(unsigned int)key);

        float4 bx = make_float4(0.f, 0.f, 0.f, 0.f);
        float  so = 0.f, lab = -1.f;
        if (scv > 0.0f && flat >= 0 && flat < NFLAT){
            int c    = flat >> 8;
            int slot = flat & 255;
            bx  = g_box4[(b*NC + c)*KC + slot];
            so  = scv;
            lab = (float)c;
        }
        float* ob = out;                       // [B, MAXT, 4]
        float* os = out + BATCH*MAXT*4;        // [B, MAXT]
        float* ol = out + BATCH*MAXT*5;        // [B, MAXT]
        reinterpret_cast<float4*>(ob)[b*MAXT + tid] = bx;
        os[b*MAXT + tid] = so;
        ol[b*MAXT + tid] = lab;
    }
}

// ---------------- launch ----------------------------------------------------
extern "C" void kernel_launch(void* const* d_in, const int* in_sizes, int n_in,
                              void* d_out, int out_size){
    const float* box_pred = (const float*)d_in[0];   // [B, A, 4]
    const float* cls_pred = (const float*)d_in[1];   // [B, A, C]
    const float* anchors  = (const float*)d_in[2];   // [A, 4]
    float* out = (float*)d_out;

    cudaFuncSetAttribute(k_final, cudaFuncAttributeMaxDynamicSharedMemorySize,
                         NFLAT*sizeof(unsigned int));

    k_filter<<<BATCH*BPB, FBLK>>>(cls_pred);
    k_select<<<BC, SBLK>>>(cls_pred, box_pred, anchors);
    k_final<<<BATCH, 1024, NFLAT*sizeof(unsigned int)>>>(out);
}